// round 15
// baseline (speedup 1.0000x reference)
#include <cuda_runtime.h>
#include <cuda_fp16.h>
#include <math.h>
#include <stdint.h>

#define BATCH 8192
#define HID   1024
#define FH    96
#define O_DIM 8
#define E_DIM 36
#define NM    768
#define NV    3456
#define NCAT  (NM + NV)     // 4224

// ---------------------------------------------------------------------------
// Device scratch (allocation-free per harness rules)
// ---------------------------------------------------------------------------
__device__ __half g_zhi[(size_t)BATCH * HID];
__device__ __half g_ihi[(size_t)BATCH * HID];
__device__ __half g_hhi[(size_t)BATCH * HID];
__device__ __half g_w1hi[(size_t)HID * HID];
__device__ __half g_w2hi[(size_t)HID * HID];
__device__ __half g_wchi[(size_t)NCAT * HID];   // [Wm|Wv]^T hi
__device__ float  g_bcat[NCAT];
__device__ __half g_lv[(size_t)BATCH * NV];     // fp16 log_var

// ---------------------------------------------------------------------------
// helpers
// ---------------------------------------------------------------------------
__device__ __forceinline__ uint32_t smem_u32(const void* p) {
    uint32_t a;
    asm("{ .reg .u64 t; cvta.to.shared.u64 t, %1; cvt.u32.u64 %0, t; }" : "=r"(a) : "l"(p));
    return a;
}

__device__ __forceinline__ void cp16(uint32_t dst, const void* src) {
    asm volatile("cp.async.cg.shared.global [%0], [%1], 16;" :: "r"(dst), "l"(src));
}
#define CP_COMMIT() asm volatile("cp.async.commit_group;" ::: "memory")
#define CP_WAIT0()  asm volatile("cp.async.wait_group 0;"  ::: "memory")
#define CP_WAIT2()  asm volatile("cp.async.wait_group 2;"  ::: "memory")

__device__ __forceinline__ void ldsm4(uint32_t* r, uint32_t addr) {
    asm volatile("ldmatrix.sync.aligned.m8n8.x4.shared.b16 {%0,%1,%2,%3}, [%4];"
        : "=r"(r[0]), "=r"(r[1]), "=r"(r[2]), "=r"(r[3]) : "r"(addr));
}

__device__ __forceinline__ void mma16816(float* d, const uint32_t* a, const uint32_t* b)
{
    asm volatile(
        "mma.sync.aligned.m16n8k16.row.col.f32.f16.f16.f32 "
        "{%0,%1,%2,%3},{%4,%5,%6,%7},{%8,%9},{%0,%1,%2,%3};\n"
        : "+f"(d[0]), "+f"(d[1]), "+f"(d[2]), "+f"(d[3])
        : "r"(a[0]), "r"(a[1]), "r"(a[2]), "r"(a[3]), "r"(b[0]), "r"(b[1]));
}

__device__ __forceinline__ uint32_t hpack2(float a, float b) {
    __half2 t = __halves2half2(__float2half_rn(a), __float2half_rn(b));
    return *reinterpret_cast<uint32_t*>(&t);
}

// ---------------------------------------------------------------------------
// cvt_act: fp32 [n] -> fp16 hi [n]
// ---------------------------------------------------------------------------
__global__ __launch_bounds__(256)
void cvt_act(const float* __restrict__ x, __half* __restrict__ hi)
{
    size_t idx = ((size_t)blockIdx.x * blockDim.x + threadIdx.x) * 4;
    float4 v = *(const float4*)(x + idx);
    uint2 hp;
    hp.x = hpack2(v.x, v.y);
    hp.y = hpack2(v.z, v.w);
    *(uint2*)(hi + idx) = hp;
}

// ---------------------------------------------------------------------------
// convert all weights + concat bias in ONE launch:
//   x-tiles: [0,32) W1 | [32,64) W2 | [64,88) Wm -> wc | [88,196) Wv -> wc+NM*K
// Block (0,0) additionally writes bcat.
// ---------------------------------------------------------------------------
__global__ __launch_bounds__(256)
void convert_w_all(const float* __restrict__ W1, const float* __restrict__ W2,
                   const float* __restrict__ Wm, const float* __restrict__ Wv,
                   __half* __restrict__ w1t, __half* __restrict__ w2t,
                   __half* __restrict__ wct,
                   const float* __restrict__ bm, const float* __restrict__ bv,
                   float* __restrict__ bcat)
{
    constexpr int K = HID;
    const int bx = blockIdx.x;
    const float* W; __half* Wt; int N; int xt;
    if (bx < 32)       { W = W1; Wt = w1t; N = HID; xt = bx; }
    else if (bx < 64)  { W = W2; Wt = w2t; N = HID; xt = bx - 32; }
    else if (bx < 88)  { W = Wm; Wt = wct; N = NM;  xt = bx - 64; }
    else               { W = Wv; Wt = wct + (size_t)NM * K; N = NV; xt = bx - 88; }

    __shared__ float tile[32][33];
    const int k0 = blockIdx.y * 32, n0 = xt * 32;
    const int tx = threadIdx.x & 31, ty = threadIdx.x >> 5;
#pragma unroll
    for (int r = ty; r < 32; r += 8)
        tile[r][tx] = W[(size_t)(k0 + r) * N + n0 + tx];
    __syncthreads();
#pragma unroll
    for (int i = threadIdx.x; i < 32 * 16; i += 256) {
        int nl = i >> 4, kp = i & 15;
        float a = tile[2 * kp][nl], b = tile[2 * kp + 1][nl];
        size_t base = (size_t)(n0 + nl) * K + k0 + 2 * kp;
        *(uint32_t*)(Wt + base) = hpack2(a, b);
    }
    if (bx == 0 && blockIdx.y == 0) {
        for (int i = threadIdx.x; i < NCAT; i += 256)
            bcat[i] = (i < NM) ? bm[i] : bv[i - NM];
    }
}

// ---------------------------------------------------------------------------
// fp16 GEMM: C[M,N] = act(A_hi @ B_hi^T + bias)   (single pass, BK=32)
// CTA 128x128, 8 warps 2Mx4N, warp 64x32 (MT4 NT4). 2 CTAs/SM.
// 4-stage cp.async pipeline (prefetch distance 3), ldmatrix, indep. MMA sweeps.
// OUTMODE 3: fp16 out (Chi), N must be HID.
// OUTMODE 2: cols [0,NM) -> fp32 Cf0 (stride NM), [NM,NCAT) -> fp16 Clv (stride NV).
// ---------------------------------------------------------------------------
template <bool SILU, int OUTMODE>
__global__ __launch_bounds__(256, 2)
void gemm_mma(const __half* __restrict__ Ahi,
              const __half* __restrict__ Bthi,
              const float* __restrict__ bias,
              float* __restrict__ Cf0, __half* __restrict__ Clv,
              __half* __restrict__ Chi)
{
    constexpr int K = HID;
    constexpr int BK = 32;
    constexpr int NITER = K / BK;          // 32 stages
    constexpr int NSTG = 4;
    constexpr int RS = 80;                 // 32 fp16 = 64B + 16B pad
    constexpr int MT = 4, NT = 4;
    constexpr int CTAM = 128;
    constexpr int WMCNT = CTAM / (MT * 16);    // 2
    constexpr int SA_HI = 0;
    constexpr int SB_HI = CTAM * RS;           // 10240
    constexpr int STAGE = SB_HI + 128 * RS;    // 20480
    constexpr int BIASOFF = NSTG * STAGE;      // 81920

    extern __shared__ __align__(128) char smem[];
    const uint32_t sb = smem_u32(smem);
    float* sBias = (float*)(smem + BIASOFF);

    const int tid  = threadIdx.x;
    const int lane = tid & 31;
    const int wid  = tid >> 5;
    const int g = lane >> 2;               // 0..7
    const int t = lane & 3;                // 0..3
    const int m0 = (wid % WMCNT) * (MT * 16);
    const int n0 = (wid / WMCNT) * (NT * 8);

    const int blockM = blockIdx.y * CTAM;
    const int blockN = blockIdx.x * 128;

    if (tid < 128) sBias[tid] = bias[blockN + tid];

    const uint32_t aoff = (uint32_t)(m0 + (lane & 15)) * RS + (uint32_t)(lane >> 4) * 16;
    const uint32_t boff = (uint32_t)(n0 + ((lane >> 4) << 3) + (lane & 7)) * RS
                        + (uint32_t)((lane >> 3) & 1) * 16;

    const __half* Ahi_b = Ahi + (size_t)blockM * K;
    const __half* Bhi_b = Bthi + (size_t)blockN * K;

    auto load_stage = [&](int s) {
        const int k0 = s * BK;
        const uint32_t buf = sb + (s % NSTG) * STAGE;
        const int row = tid >> 1, ch = (tid & 1) * 2;
        const size_t goff = (size_t)row * K + k0 + ch * 8;
        const uint32_t soff = row * RS + ch * 16;
        cp16(buf + SA_HI + soff,      Ahi_b + goff);
        cp16(buf + SA_HI + soff + 16, Ahi_b + goff + 8);
        cp16(buf + SB_HI + soff,      Bhi_b + goff);
        cp16(buf + SB_HI + soff + 16, Bhi_b + goff + 8);
    };

    float acc[MT][NT][4];
#pragma unroll
    for (int mt = 0; mt < MT; mt++)
#pragma unroll
        for (int nt = 0; nt < NT; nt++)
#pragma unroll
            for (int c = 0; c < 4; c++) acc[mt][nt][c] = 0.f;

    load_stage(0); CP_COMMIT();
    load_stage(1); CP_COMMIT();
    load_stage(2); CP_COMMIT();

    for (int it = 0; it < NITER; ++it) {
        if (it >= NITER - 3) { CP_WAIT0(); } else { CP_WAIT2(); }
        __syncthreads();
        if (it + 3 < NITER) { load_stage(it + 3); CP_COMMIT(); }

        const uint32_t buf = sb + (it % NSTG) * STAGE;

#pragma unroll
        for (int ks = 0; ks < 2; ks++) {
            const uint32_t aHi = buf + SA_HI + aoff + ks * 32;
            const uint32_t bHi = buf + SB_HI + boff + ks * 32;

            uint32_t fAhi[MT][4], fBhi[NT][2];
#pragma unroll
            for (int mt = 0; mt < MT; mt++)
                ldsm4(fAhi[mt], aHi + mt * 16 * RS);
#pragma unroll
            for (int nt = 0; nt < NT; nt += 2)
                ldsm4(&fBhi[nt][0], bHi + nt * 8 * RS);

#pragma unroll
            for (int mt = 0; mt < MT; mt++)
#pragma unroll
                for (int nt = 0; nt < NT; nt++)
                    mma16816(acc[mt][nt], fAhi[mt], fBhi[nt]);
        }
    }

    // epilogue
    const bool isMeans = (OUTMODE == 2) && (blockN < NM);
#pragma unroll
    for (int mt = 0; mt < MT; mt++) {
        const int row0 = blockM + m0 + mt * 16 + g;
#pragma unroll
        for (int nt = 0; nt < NT; nt++) {
            const int coll = n0 + nt * 8 + 2 * t;
            const float bv0 = sBias[coll], bv1 = sBias[coll + 1];
            float v00 = acc[mt][nt][0] + bv0, v01 = acc[mt][nt][1] + bv1;
            float v10 = acc[mt][nt][2] + bv0, v11 = acc[mt][nt][3] + bv1;
            if (SILU) {
                v00 = v00 / (1.f + expf(-v00));
                v01 = v01 / (1.f + expf(-v01));
                v10 = v10 / (1.f + expf(-v10));
                v11 = v11 / (1.f + expf(-v11));
            }
            if (OUTMODE == 2) {
                if (isMeans) {
                    const int col = blockN + coll;
                    float2 a = {v00, v01}, b = {v10, v11};
                    *(float2*)(Cf0 + (size_t)row0 * NM + col)       = a;
                    *(float2*)(Cf0 + (size_t)(row0 + 8) * NM + col) = b;
                } else {
                    const int col = blockN - NM + coll;
                    *(uint32_t*)(Clv + (size_t)row0 * NV + col)       = hpack2(v00, v01);
                    *(uint32_t*)(Clv + (size_t)(row0 + 8) * NV + col) = hpack2(v10, v11);
                }
            } else {
                const int col = blockN + coll;
                size_t p0 = (size_t)row0 * HID + col;
                size_t p1 = (size_t)(row0 + 8) * HID + col;
                *(uint32_t*)(Chi + p0) = hpack2(v00, v01);
                *(uint32_t*)(Chi + p1) = hpack2(v10, v11);
            }
        }
    }
}

// ---------------------------------------------------------------------------
// MVN epilogue: 16 threads per (b,h) group, float4 stores, fp16 lv input.
// ---------------------------------------------------------------------------
__device__ __forceinline__ int triu_idx(int r, int c) {
    return r * (15 - r) / 2 + (c - r - 1);
}

__global__ __launch_bounds__(256)
void mvn_epilogue(const __half* __restrict__ lv,
                  float* __restrict__ prec,
                  float* __restrict__ Dout,
                  float* __restrict__ Tout)
{
    constexpr int GP = 16;                 // groups per block (16 threads each)
    __shared__ float s_eta[GP][E_DIM];
    __shared__ float s_d[GP][O_DIM];
    __shared__ float s_dinv[GP][O_DIM];

    const int g = threadIdx.x >> 4;        // 0..15
    const int s = threadIdx.x & 15;        // 0..15
    const size_t bh = (size_t)blockIdx.x * GP + g;

#pragma unroll
    for (int e = s; e < E_DIM; e += 16)
        s_eta[g][e] = __half2float(lv[bh * E_DIM + e]);
    __syncthreads();
    if (s < O_DIM) {
        float d = expf(0.5f * s_eta[g][s]);
        s_d[g][s] = d;
        s_dinv[g][s] = 1.f / d;
    }
    __syncthreads();

    const int i  = s >> 1;                 // row 0..7
    const int kb = (s & 1) * 4;            // col base 0 or 4
    const float* e = s_eta[g];
    const float* dinv = s_dinv[g];

    float pv[4] = {0.f, 0.f, 0.f, 0.f};
    float tv[4], dv[4];
#pragma unroll
    for (int c = 0; c < 4; c++) {
        const int k = kb + c;
        tv[c] = (i == k) ? 1.f : ((i < k) ? e[O_DIM + triu_idx(i, k)] : 0.f);
        dv[c] = (i == k) ? s_d[g][i] : 0.f;
    }
#pragma unroll
    for (int j = 0; j < O_DIM; j++) {
        float tji = (j == i) ? 1.f : ((j < i) ? e[O_DIM + triu_idx(j, i)] : 0.f);
        float w = tji * dinv[j];
#pragma unroll
        for (int c = 0; c < 4; c++) {
            const int k = kb + c;
            float tjk = (j == k) ? 1.f : ((j < k) ? e[O_DIM + triu_idx(j, k)] : 0.f);
            pv[c] = fmaf(w, tjk, pv[c]);
        }
    }

    const size_t base = bh * (O_DIM * O_DIM) + i * O_DIM + kb;
    *(float4*)(prec + base) = *(float4*)pv;
    *(float4*)(Dout + base) = *(float4*)dv;
    *(float4*)(Tout + base) = *(float4*)tv;
}

// ---------------------------------------------------------------------------
// Launch
// ---------------------------------------------------------------------------
extern "C" void kernel_launch(void* const* d_in, const int* in_sizes, int n_in,
                              void* d_out, int out_size)
{
    const float* z  = (const float*)d_in[0];
    const float* W1 = (const float*)d_in[1];
    const float* b1 = (const float*)d_in[2];
    const float* W2 = (const float*)d_in[3];
    const float* b2 = (const float*)d_in[4];
    const float* Wm = (const float*)d_in[5];
    const float* bm = (const float*)d_in[6];
    const float* Wv = (const float*)d_in[7];
    const float* bv = (const float*)d_in[8];

    float* out = (float*)d_out;
    const size_t n_means = (size_t)BATCH * FH * O_DIM;
    const size_t n_mat   = (size_t)BATCH * FH * O_DIM * O_DIM;
    float* means = out;
    float* prec  = out + n_means;
    float* Dout  = prec + n_mat;
    float* Tout  = Dout + n_mat;

    __half *zhi, *ihi, *hhi, *w1hi, *w2hi, *wchi, *lv;
    float *bcat;
    cudaGetSymbolAddress((void**)&zhi, g_zhi);
    cudaGetSymbolAddress((void**)&ihi, g_ihi);
    cudaGetSymbolAddress((void**)&hhi, g_hhi);
    cudaGetSymbolAddress((void**)&w1hi, g_w1hi);
    cudaGetSymbolAddress((void**)&w2hi, g_w2hi);
    cudaGetSymbolAddress((void**)&wchi, g_wchi);
    cudaGetSymbolAddress((void**)&bcat, g_bcat);
    cudaGetSymbolAddress((void**)&lv, g_lv);

    const int SMEM = 4 * 20480 + 512;   // 82432
    cudaFuncSetAttribute((void*)gemm_mma<true, 3>,  cudaFuncAttributeMaxDynamicSharedMemorySize, SMEM);
    cudaFuncSetAttribute((void*)gemm_mma<false, 3>, cudaFuncAttributeMaxDynamicSharedMemorySize, SMEM);
    cudaFuncSetAttribute((void*)gemm_mma<false, 2>, cudaFuncAttributeMaxDynamicSharedMemorySize, SMEM);

    // converts: 2 launches
    cvt_act<<<(BATCH * HID / 4) / 256, 256>>>(z, zhi);
    convert_w_all<<<dim3(196, HID / 32), 256>>>(W1, W2, Wm, Wv, w1hi, w2hi, wchi,
                                                bm, bv, bcat);

    // GEMM chain (single-pass fp16, CTA 128x128, BK=32, 4-stage, 2 CTAs/SM)
    gemm_mma<true, 3><<<dim3(HID / 128, BATCH / 128), 256, SMEM>>>(
        zhi, w1hi, b1, nullptr, nullptr, ihi);
    gemm_mma<false, 3><<<dim3(HID / 128, BATCH / 128), 256, SMEM>>>(
        ihi, w2hi, b2, nullptr, nullptr, hhi);
    gemm_mma<false, 2><<<dim3(NCAT / 128, BATCH / 128), 256, SMEM>>>(
        hhi, wchi, bcat, means, lv, nullptr);

    // MVN epilogue (16 groups/block, float4 stores, fp16 lv)
    mvn_epilogue<<<(BATCH * FH) / 16, 256>>>(lv, prec, Dout, Tout);
}

// round 16
// speedup vs baseline: 1.0114x; 1.0114x over previous
#include <cuda_runtime.h>
#include <cuda_fp16.h>
#include <math.h>
#include <stdint.h>

#define BATCH 8192
#define HID   1024
#define FH    96
#define O_DIM 8
#define E_DIM 36
#define NM    768
#define NV    3456
#define NCAT  (NM + NV)     // 4224

// ---------------------------------------------------------------------------
// Device scratch (allocation-free per harness rules)
// ---------------------------------------------------------------------------
__device__ __half g_zhi[(size_t)BATCH * HID];
__device__ __half g_ihi[(size_t)BATCH * HID];
__device__ __half g_hhi[(size_t)BATCH * HID];
__device__ __half g_w1hi[(size_t)HID * HID];
__device__ __half g_w2hi[(size_t)HID * HID];
__device__ __half g_wchi[(size_t)NCAT * HID];   // [Wm|Wv]^T hi
__device__ float  g_bcat[NCAT];
__device__ __half g_lv[(size_t)BATCH * NV];     // fp16 log_var

// ---------------------------------------------------------------------------
// helpers
// ---------------------------------------------------------------------------
__device__ __forceinline__ uint32_t smem_u32(const void* p) {
    uint32_t a;
    asm("{ .reg .u64 t; cvta.to.shared.u64 t, %1; cvt.u32.u64 %0, t; }" : "=r"(a) : "l"(p));
    return a;
}

__device__ __forceinline__ void cp16(uint32_t dst, const void* src) {
    asm volatile("cp.async.cg.shared.global [%0], [%1], 16;" :: "r"(dst), "l"(src));
}
#define CP_COMMIT() asm volatile("cp.async.commit_group;" ::: "memory")
#define CP_WAIT0()  asm volatile("cp.async.wait_group 0;"  ::: "memory")
#define CP_WAIT1()  asm volatile("cp.async.wait_group 1;"  ::: "memory")

__device__ __forceinline__ void ldsm4(uint32_t* r, uint32_t addr) {
    asm volatile("ldmatrix.sync.aligned.m8n8.x4.shared.b16 {%0,%1,%2,%3}, [%4];"
        : "=r"(r[0]), "=r"(r[1]), "=r"(r[2]), "=r"(r[3]) : "r"(addr));
}

__device__ __forceinline__ void mma16816(float* d, const uint32_t* a, const uint32_t* b)
{
    asm volatile(
        "mma.sync.aligned.m16n8k16.row.col.f32.f16.f16.f32 "
        "{%0,%1,%2,%3},{%4,%5,%6,%7},{%8,%9},{%0,%1,%2,%3};\n"
        : "+f"(d[0]), "+f"(d[1]), "+f"(d[2]), "+f"(d[3])
        : "r"(a[0]), "r"(a[1]), "r"(a[2]), "r"(a[3]), "r"(b[0]), "r"(b[1]));
}

__device__ __forceinline__ uint32_t hpack2(float a, float b) {
    __half2 t = __halves2half2(__float2half_rn(a), __float2half_rn(b));
    return *reinterpret_cast<uint32_t*>(&t);
}

// ---------------------------------------------------------------------------
// cvt_act: fp32 [n] -> fp16 hi [n]
// ---------------------------------------------------------------------------
__global__ __launch_bounds__(256)
void cvt_act(const float* __restrict__ x, __half* __restrict__ hi)
{
    size_t idx = ((size_t)blockIdx.x * blockDim.x + threadIdx.x) * 4;
    float4 v = *(const float4*)(x + idx);
    uint2 hp;
    hp.x = hpack2(v.x, v.y);
    hp.y = hpack2(v.z, v.w);
    *(uint2*)(hi + idx) = hp;
}

// ---------------------------------------------------------------------------
// convert all weights + concat bias in ONE launch:
//   x-tiles: [0,32) W1 | [32,64) W2 | [64,88) Wm -> wc | [88,196) Wv -> wc+NM*K
// Block (0,0) additionally writes bcat.
// ---------------------------------------------------------------------------
__global__ __launch_bounds__(256)
void convert_w_all(const float* __restrict__ W1, const float* __restrict__ W2,
                   const float* __restrict__ Wm, const float* __restrict__ Wv,
                   __half* __restrict__ w1t, __half* __restrict__ w2t,
                   __half* __restrict__ wct,
                   const float* __restrict__ bm, const float* __restrict__ bv,
                   float* __restrict__ bcat)
{
    constexpr int K = HID;
    const int bx = blockIdx.x;
    const float* W; __half* Wt; int N; int xt;
    if (bx < 32)       { W = W1; Wt = w1t; N = HID; xt = bx; }
    else if (bx < 64)  { W = W2; Wt = w2t; N = HID; xt = bx - 32; }
    else if (bx < 88)  { W = Wm; Wt = wct; N = NM;  xt = bx - 64; }
    else               { W = Wv; Wt = wct + (size_t)NM * K; N = NV; xt = bx - 88; }

    __shared__ float tile[32][33];
    const int k0 = blockIdx.y * 32, n0 = xt * 32;
    const int tx = threadIdx.x & 31, ty = threadIdx.x >> 5;
#pragma unroll
    for (int r = ty; r < 32; r += 8)
        tile[r][tx] = W[(size_t)(k0 + r) * N + n0 + tx];
    __syncthreads();
#pragma unroll
    for (int i = threadIdx.x; i < 32 * 16; i += 256) {
        int nl = i >> 4, kp = i & 15;
        float a = tile[2 * kp][nl], b = tile[2 * kp + 1][nl];
        size_t base = (size_t)(n0 + nl) * K + k0 + 2 * kp;
        *(uint32_t*)(Wt + base) = hpack2(a, b);
    }
    if (bx == 0 && blockIdx.y == 0) {
        for (int i = threadIdx.x; i < NCAT; i += 256)
            bcat[i] = (i < NM) ? bm[i] : bv[i - NM];
    }
}

// ---------------------------------------------------------------------------
// fp16 GEMM: C[M,N] = act(A_hi @ B_hi^T + bias)   (single pass, BK=32)
// CTA 128x128, 8 warps 2Mx4N, warp 64x32 (MT4 NT4). 2 CTAs/SM.
// 3-stage cp.async pipeline (prefetch distance 2), ldmatrix, indep. MMA sweeps.
// OUTMODE 3: fp16 out (Chi), N must be HID.
// OUTMODE 2: cols [0,NM) -> fp32 Cf0 (stride NM), [NM,NCAT) -> fp16 Clv (stride NV).
// ---------------------------------------------------------------------------
template <bool SILU, int OUTMODE>
__global__ __launch_bounds__(256, 2)
void gemm_mma(const __half* __restrict__ Ahi,
              const __half* __restrict__ Bthi,
              const float* __restrict__ bias,
              float* __restrict__ Cf0, __half* __restrict__ Clv,
              __half* __restrict__ Chi)
{
    constexpr int K = HID;
    constexpr int BK = 32;
    constexpr int NITER = K / BK;          // 32 stages
    constexpr int NSTG = 3;
    constexpr int RS = 80;                 // 32 fp16 = 64B + 16B pad
    constexpr int MT = 4, NT = 4;
    constexpr int CTAM = 128;
    constexpr int WMCNT = CTAM / (MT * 16);    // 2
    constexpr int SA_HI = 0;
    constexpr int SB_HI = CTAM * RS;           // 10240
    constexpr int STAGE = SB_HI + 128 * RS;    // 20480
    constexpr int BIASOFF = NSTG * STAGE;      // 61440

    extern __shared__ __align__(128) char smem[];
    const uint32_t sb = smem_u32(smem);
    float* sBias = (float*)(smem + BIASOFF);

    const int tid  = threadIdx.x;
    const int lane = tid & 31;
    const int wid  = tid >> 5;
    const int g = lane >> 2;               // 0..7
    const int t = lane & 3;                // 0..3
    const int m0 = (wid % WMCNT) * (MT * 16);
    const int n0 = (wid / WMCNT) * (NT * 8);

    const int blockM = blockIdx.y * CTAM;
    const int blockN = blockIdx.x * 128;

    if (tid < 128) sBias[tid] = bias[blockN + tid];

    const uint32_t aoff = (uint32_t)(m0 + (lane & 15)) * RS + (uint32_t)(lane >> 4) * 16;
    const uint32_t boff = (uint32_t)(n0 + ((lane >> 4) << 3) + (lane & 7)) * RS
                        + (uint32_t)((lane >> 3) & 1) * 16;

    const __half* Ahi_b = Ahi + (size_t)blockM * K;
    const __half* Bhi_b = Bthi + (size_t)blockN * K;

    auto load_stage = [&](int s) {
        const int k0 = s * BK;
        const uint32_t buf = sb + (s % NSTG) * STAGE;
        const int row = tid >> 1, ch = (tid & 1) * 2;
        const size_t goff = (size_t)row * K + k0 + ch * 8;
        const uint32_t soff = row * RS + ch * 16;
        cp16(buf + SA_HI + soff,      Ahi_b + goff);
        cp16(buf + SA_HI + soff + 16, Ahi_b + goff + 8);
        cp16(buf + SB_HI + soff,      Bhi_b + goff);
        cp16(buf + SB_HI + soff + 16, Bhi_b + goff + 8);
    };

    float acc[MT][NT][4];
#pragma unroll
    for (int mt = 0; mt < MT; mt++)
#pragma unroll
        for (int nt = 0; nt < NT; nt++)
#pragma unroll
            for (int c = 0; c < 4; c++) acc[mt][nt][c] = 0.f;

    load_stage(0); CP_COMMIT();
    load_stage(1); CP_COMMIT();

    for (int it = 0; it < NITER; ++it) {
        if (it == NITER - 1) { CP_WAIT0(); } else { CP_WAIT1(); }
        __syncthreads();
        if (it + 2 < NITER) { load_stage(it + 2); CP_COMMIT(); }

        const uint32_t buf = sb + (it % NSTG) * STAGE;

#pragma unroll
        for (int ks = 0; ks < 2; ks++) {
            const uint32_t aHi = buf + SA_HI + aoff + ks * 32;
            const uint32_t bHi = buf + SB_HI + boff + ks * 32;

            uint32_t fAhi[MT][4], fBhi[NT][2];
#pragma unroll
            for (int mt = 0; mt < MT; mt++)
                ldsm4(fAhi[mt], aHi + mt * 16 * RS);
#pragma unroll
            for (int nt = 0; nt < NT; nt += 2)
                ldsm4(&fBhi[nt][0], bHi + nt * 8 * RS);

#pragma unroll
            for (int mt = 0; mt < MT; mt++)
#pragma unroll
                for (int nt = 0; nt < NT; nt++)
                    mma16816(acc[mt][nt], fAhi[mt], fBhi[nt]);
        }
    }

    // epilogue
    const bool isMeans = (OUTMODE == 2) && (blockN < NM);
#pragma unroll
    for (int mt = 0; mt < MT; mt++) {
        const int row0 = blockM + m0 + mt * 16 + g;
#pragma unroll
        for (int nt = 0; nt < NT; nt++) {
            const int coll = n0 + nt * 8 + 2 * t;
            const float bv0 = sBias[coll], bv1 = sBias[coll + 1];
            float v00 = acc[mt][nt][0] + bv0, v01 = acc[mt][nt][1] + bv1;
            float v10 = acc[mt][nt][2] + bv0, v11 = acc[mt][nt][3] + bv1;
            if (SILU) {
                v00 = v00 / (1.f + expf(-v00));
                v01 = v01 / (1.f + expf(-v01));
                v10 = v10 / (1.f + expf(-v10));
                v11 = v11 / (1.f + expf(-v11));
            }
            if (OUTMODE == 2) {
                if (isMeans) {
                    const int col = blockN + coll;
                    float2 a = {v00, v01}, b = {v10, v11};
                    *(float2*)(Cf0 + (size_t)row0 * NM + col)       = a;
                    *(float2*)(Cf0 + (size_t)(row0 + 8) * NM + col) = b;
                } else {
                    const int col = blockN - NM + coll;
                    *(uint32_t*)(Clv + (size_t)row0 * NV + col)       = hpack2(v00, v01);
                    *(uint32_t*)(Clv + (size_t)(row0 + 8) * NV + col) = hpack2(v10, v11);
                }
            } else {
                const int col = blockN + coll;
                size_t p0 = (size_t)row0 * HID + col;
                size_t p1 = (size_t)(row0 + 8) * HID + col;
                *(uint32_t*)(Chi + p0) = hpack2(v00, v01);
                *(uint32_t*)(Chi + p1) = hpack2(v10, v11);
            }
        }
    }
}

// ---------------------------------------------------------------------------
// MVN epilogue: 16 threads per (b,h) group, float4 stores, fp16 lv input.
// ---------------------------------------------------------------------------
__device__ __forceinline__ int triu_idx(int r, int c) {
    return r * (15 - r) / 2 + (c - r - 1);
}

__global__ __launch_bounds__(256)
void mvn_epilogue(const __half* __restrict__ lv,
                  float* __restrict__ prec,
                  float* __restrict__ Dout,
                  float* __restrict__ Tout)
{
    constexpr int GP = 16;                 // groups per block (16 threads each)
    __shared__ float s_eta[GP][E_DIM];
    __shared__ float s_d[GP][O_DIM];
    __shared__ float s_dinv[GP][O_DIM];

    const int g = threadIdx.x >> 4;        // 0..15
    const int s = threadIdx.x & 15;        // 0..15
    const size_t bh = (size_t)blockIdx.x * GP + g;

#pragma unroll
    for (int e = s; e < E_DIM; e += 16)
        s_eta[g][e] = __half2float(lv[bh * E_DIM + e]);
    __syncthreads();
    if (s < O_DIM) {
        float d = expf(0.5f * s_eta[g][s]);
        s_d[g][s] = d;
        s_dinv[g][s] = 1.f / d;
    }
    __syncthreads();

    const int i  = s >> 1;                 // row 0..7
    const int kb = (s & 1) * 4;            // col base 0 or 4
    const float* e = s_eta[g];
    const float* dinv = s_dinv[g];

    float pv[4] = {0.f, 0.f, 0.f, 0.f};
    float tv[4], dv[4];
#pragma unroll
    for (int c = 0; c < 4; c++) {
        const int k = kb + c;
        tv[c] = (i == k) ? 1.f : ((i < k) ? e[O_DIM + triu_idx(i, k)] : 0.f);
        dv[c] = (i == k) ? s_d[g][i] : 0.f;
    }
#pragma unroll
    for (int j = 0; j < O_DIM; j++) {
        float tji = (j == i) ? 1.f : ((j < i) ? e[O_DIM + triu_idx(j, i)] : 0.f);
        float w = tji * dinv[j];
#pragma unroll
        for (int c = 0; c < 4; c++) {
            const int k = kb + c;
            float tjk = (j == k) ? 1.f : ((j < k) ? e[O_DIM + triu_idx(j, k)] : 0.f);
            pv[c] = fmaf(w, tjk, pv[c]);
        }
    }

    const size_t base = bh * (O_DIM * O_DIM) + i * O_DIM + kb;
    *(float4*)(prec + base) = *(float4*)pv;
    *(float4*)(Dout + base) = *(float4*)dv;
    *(float4*)(Tout + base) = *(float4*)tv;
}

// ---------------------------------------------------------------------------
// Launch
// ---------------------------------------------------------------------------
extern "C" void kernel_launch(void* const* d_in, const int* in_sizes, int n_in,
                              void* d_out, int out_size)
{
    const float* z  = (const float*)d_in[0];
    const float* W1 = (const float*)d_in[1];
    const float* b1 = (const float*)d_in[2];
    const float* W2 = (const float*)d_in[3];
    const float* b2 = (const float*)d_in[4];
    const float* Wm = (const float*)d_in[5];
    const float* bm = (const float*)d_in[6];
    const float* Wv = (const float*)d_in[7];
    const float* bv = (const float*)d_in[8];

    float* out = (float*)d_out;
    const size_t n_means = (size_t)BATCH * FH * O_DIM;
    const size_t n_mat   = (size_t)BATCH * FH * O_DIM * O_DIM;
    float* means = out;
    float* prec  = out + n_means;
    float* Dout  = prec + n_mat;
    float* Tout  = Dout + n_mat;

    __half *zhi, *ihi, *hhi, *w1hi, *w2hi, *wchi, *lv;
    float *bcat;
    cudaGetSymbolAddress((void**)&zhi, g_zhi);
    cudaGetSymbolAddress((void**)&ihi, g_ihi);
    cudaGetSymbolAddress((void**)&hhi, g_hhi);
    cudaGetSymbolAddress((void**)&w1hi, g_w1hi);
    cudaGetSymbolAddress((void**)&w2hi, g_w2hi);
    cudaGetSymbolAddress((void**)&wchi, g_wchi);
    cudaGetSymbolAddress((void**)&bcat, g_bcat);
    cudaGetSymbolAddress((void**)&lv, g_lv);

    const int SMEM = 3 * 20480 + 512;   // 61952
    cudaFuncSetAttribute((void*)gemm_mma<true, 3>,  cudaFuncAttributeMaxDynamicSharedMemorySize, SMEM);
    cudaFuncSetAttribute((void*)gemm_mma<false, 3>, cudaFuncAttributeMaxDynamicSharedMemorySize, SMEM);
    cudaFuncSetAttribute((void*)gemm_mma<false, 2>, cudaFuncAttributeMaxDynamicSharedMemorySize, SMEM);

    // converts: 2 launches
    cvt_act<<<(BATCH * HID / 4) / 256, 256>>>(z, zhi);
    convert_w_all<<<dim3(196, HID / 32), 256>>>(W1, W2, Wm, Wv, w1hi, w2hi, wchi,
                                                bm, bv, bcat);

    // GEMM chain (single-pass fp16, CTA 128x128, BK=32, 3-stage, 2 CTAs/SM)
    gemm_mma<true, 3><<<dim3(HID / 128, BATCH / 128), 256, SMEM>>>(
        zhi, w1hi, b1, nullptr, nullptr, ihi);
    gemm_mma<false, 3><<<dim3(HID / 128, BATCH / 128), 256, SMEM>>>(
        ihi, w2hi, b2, nullptr, nullptr, hhi);
    gemm_mma<false, 2><<<dim3(NCAT / 128, BATCH / 128), 256, SMEM>>>(
        hhi, wchi, bcat, means, lv, nullptr);

    // MVN epilogue (16 groups/block, float4 stores, fp16 lv)
    mvn_epilogue<<<(BATCH * FH) / 16, 256>>>(lv, prec, Dout, Tout);
}

// round 17
// speedup vs baseline: 1.0993x; 1.0869x over previous
#include <cuda_runtime.h>
#include <cuda_fp16.h>
#include <math.h>
#include <stdint.h>

#define BATCH 8192
#define HID   1024
#define FH    96
#define O_DIM 8
#define E_DIM 36
#define NM    768
#define NV    3456
#define NCAT  (NM + NV)     // 4224

// ---------------------------------------------------------------------------
// Device scratch (allocation-free per harness rules)
// ---------------------------------------------------------------------------
__device__ __half g_zhi[(size_t)BATCH * HID];
__device__ __half g_ihi[(size_t)BATCH * HID];
__device__ __half g_hhi[(size_t)BATCH * HID];
__device__ __half g_w1hi[(size_t)HID * HID];
__device__ __half g_w2hi[(size_t)HID * HID];
__device__ __half g_wchi[(size_t)NCAT * HID];   // [Wm|Wv]^T hi
__device__ float  g_bcat[NCAT];
__device__ float  g_lv[(size_t)BATCH * NV];     // fp32 log_var

// ---------------------------------------------------------------------------
// helpers
// ---------------------------------------------------------------------------
__device__ __forceinline__ uint32_t smem_u32(const void* p) {
    uint32_t a;
    asm("{ .reg .u64 t; cvta.to.shared.u64 t, %1; cvt.u32.u64 %0, t; }" : "=r"(a) : "l"(p));
    return a;
}

__device__ __forceinline__ void cp16(uint32_t dst, const void* src) {
    asm volatile("cp.async.cg.shared.global [%0], [%1], 16;" :: "r"(dst), "l"(src));
}
#define CP_COMMIT() asm volatile("cp.async.commit_group;" ::: "memory")
#define CP_WAIT0()  asm volatile("cp.async.wait_group 0;"  ::: "memory")
#define CP_WAIT1()  asm volatile("cp.async.wait_group 1;"  ::: "memory")

__device__ __forceinline__ void ldsm4(uint32_t* r, uint32_t addr) {
    asm volatile("ldmatrix.sync.aligned.m8n8.x4.shared.b16 {%0,%1,%2,%3}, [%4];"
        : "=r"(r[0]), "=r"(r[1]), "=r"(r[2]), "=r"(r[3]) : "r"(addr));
}

__device__ __forceinline__ void mma16816(float* d, const uint32_t* a, const uint32_t* b)
{
    asm volatile(
        "mma.sync.aligned.m16n8k16.row.col.f32.f16.f16.f32 "
        "{%0,%1,%2,%3},{%4,%5,%6,%7},{%8,%9},{%0,%1,%2,%3};\n"
        : "+f"(d[0]), "+f"(d[1]), "+f"(d[2]), "+f"(d[3])
        : "r"(a[0]), "r"(a[1]), "r"(a[2]), "r"(a[3]), "r"(b[0]), "r"(b[1]));
}

__device__ __forceinline__ uint32_t hpack2(float a, float b) {
    __half2 t = __halves2half2(__float2half_rn(a), __float2half_rn(b));
    return *reinterpret_cast<uint32_t*>(&t);
}

// ---------------------------------------------------------------------------
// Single prep kernel:
//   x-tiles [0,32)    W1 -> w1t
//   x-tiles [32,64)   W2 -> w2t
//   x-tiles [64,88)   Wm -> wct
//   x-tiles [88,196)  Wv -> wct + NM*K
//   x-tiles [196,228) z fp32 -> fp16 (chunk id = (bx-196)*32 + by, 1024 chunks)
//   block (0,0) also writes bcat.
// ---------------------------------------------------------------------------
__global__ __launch_bounds__(256)
void prep_all(const float* __restrict__ W1, const float* __restrict__ W2,
              const float* __restrict__ Wm, const float* __restrict__ Wv,
              const float* __restrict__ z,
              __half* __restrict__ w1t, __half* __restrict__ w2t,
              __half* __restrict__ wct, __half* __restrict__ zhi,
              const float* __restrict__ bm, const float* __restrict__ bv,
              float* __restrict__ bcat)
{
    constexpr int K = HID;
    const int bx = blockIdx.x;

    if (bx >= 196) {
        // z convert: 2,097,152 float4 over 1024 chunks -> 2048 float4/chunk
        const int chunk = (bx - 196) * 32 + blockIdx.y;
        size_t base4 = (size_t)chunk * 2048 + threadIdx.x;
#pragma unroll
        for (int r = 0; r < 8; r++) {
            size_t i4 = base4 + (size_t)r * 256;
            float4 v = *(const float4*)(z + i4 * 4);
            uint2 hp;
            hp.x = hpack2(v.x, v.y);
            hp.y = hpack2(v.z, v.w);
            *(uint2*)(zhi + i4 * 4) = hp;
        }
        return;
    }

    const float* W; __half* Wt; int N; int xt;
    if (bx < 32)       { W = W1; Wt = w1t; N = HID; xt = bx; }
    else if (bx < 64)  { W = W2; Wt = w2t; N = HID; xt = bx - 32; }
    else if (bx < 88)  { W = Wm; Wt = wct; N = NM;  xt = bx - 64; }
    else               { W = Wv; Wt = wct + (size_t)NM * K; N = NV; xt = bx - 88; }

    __shared__ float tile[32][33];
    const int k0 = blockIdx.y * 32, n0 = xt * 32;
    const int tx = threadIdx.x & 31, ty = threadIdx.x >> 5;
#pragma unroll
    for (int r = ty; r < 32; r += 8)
        tile[r][tx] = W[(size_t)(k0 + r) * N + n0 + tx];
    __syncthreads();
#pragma unroll
    for (int i = threadIdx.x; i < 32 * 16; i += 256) {
        int nl = i >> 4, kp = i & 15;
        float a = tile[2 * kp][nl], b = tile[2 * kp + 1][nl];
        size_t base = (size_t)(n0 + nl) * K + k0 + 2 * kp;
        *(uint32_t*)(Wt + base) = hpack2(a, b);
    }
    if (bx == 0 && blockIdx.y == 0) {
        for (int i = threadIdx.x; i < NCAT; i += 256)
            bcat[i] = (i < NM) ? bm[i] : bv[i - NM];
    }
}

// ---------------------------------------------------------------------------
// fp16 GEMM: C[M,N] = act(A_hi @ B_hi^T + bias)   (single pass, BK=32)
// CTA 128x128, 8 warps 2Mx4N, warp 64x32 (MT4 NT4). 2 CTAs/SM.
// 3-stage cp.async pipeline (prefetch distance 2), ldmatrix, indep. MMA sweeps.
// OUTMODE 3: fp16 out (Chi), N must be HID.
// OUTMODE 2: dual fp32 out: cols [0,NM) -> Cf0 (stride NM), rest -> Cf1 (stride NV).
// ---------------------------------------------------------------------------
template <bool SILU, int OUTMODE>
__global__ __launch_bounds__(256, 2)
void gemm_mma(const __half* __restrict__ Ahi,
              const __half* __restrict__ Bthi,
              const float* __restrict__ bias,
              float* __restrict__ Cf0, float* __restrict__ Cf1,
              __half* __restrict__ Chi)
{
    constexpr int K = HID;
    constexpr int BK = 32;
    constexpr int NITER = K / BK;          // 32 stages
    constexpr int NSTG = 3;
    constexpr int RS = 80;                 // 32 fp16 = 64B + 16B pad
    constexpr int MT = 4, NT = 4;
    constexpr int CTAM = 128;
    constexpr int WMCNT = CTAM / (MT * 16);    // 2
    constexpr int SA_HI = 0;
    constexpr int SB_HI = CTAM * RS;           // 10240
    constexpr int STAGE = SB_HI + 128 * RS;    // 20480
    constexpr int BIASOFF = NSTG * STAGE;      // 61440

    extern __shared__ __align__(128) char smem[];
    const uint32_t sb = smem_u32(smem);
    float* sBias = (float*)(smem + BIASOFF);

    const int tid  = threadIdx.x;
    const int lane = tid & 31;
    const int wid  = tid >> 5;
    const int g = lane >> 2;               // 0..7
    const int t = lane & 3;                // 0..3
    const int m0 = (wid % WMCNT) * (MT * 16);
    const int n0 = (wid / WMCNT) * (NT * 8);

    const int blockM = blockIdx.y * CTAM;
    const int blockN = blockIdx.x * 128;

    if (tid < 128) sBias[tid] = bias[blockN + tid];

    const uint32_t aoff = (uint32_t)(m0 + (lane & 15)) * RS + (uint32_t)(lane >> 4) * 16;
    const uint32_t boff = (uint32_t)(n0 + ((lane >> 4) << 3) + (lane & 7)) * RS
                        + (uint32_t)((lane >> 3) & 1) * 16;

    const __half* Ahi_b = Ahi + (size_t)blockM * K;
    const __half* Bhi_b = Bthi + (size_t)blockN * K;

    auto load_stage = [&](int s) {
        const int k0 = s * BK;
        const uint32_t buf = sb + (s % NSTG) * STAGE;
        const int row = tid >> 1, ch = (tid & 1) * 2;
        const size_t goff = (size_t)row * K + k0 + ch * 8;
        const uint32_t soff = row * RS + ch * 16;
        cp16(buf + SA_HI + soff,      Ahi_b + goff);
        cp16(buf + SA_HI + soff + 16, Ahi_b + goff + 8);
        cp16(buf + SB_HI + soff,      Bhi_b + goff);
        cp16(buf + SB_HI + soff + 16, Bhi_b + goff + 8);
    };

    float acc[MT][NT][4];
#pragma unroll
    for (int mt = 0; mt < MT; mt++)
#pragma unroll
        for (int nt = 0; nt < NT; nt++)
#pragma unroll
            for (int c = 0; c < 4; c++) acc[mt][nt][c] = 0.f;

    load_stage(0); CP_COMMIT();
    load_stage(1); CP_COMMIT();

    for (int it = 0; it < NITER; ++it) {
        if (it == NITER - 1) { CP_WAIT0(); } else { CP_WAIT1(); }
        __syncthreads();
        if (it + 2 < NITER) { load_stage(it + 2); CP_COMMIT(); }

        const uint32_t buf = sb + (it % NSTG) * STAGE;

#pragma unroll
        for (int ks = 0; ks < 2; ks++) {
            const uint32_t aHi = buf + SA_HI + aoff + ks * 32;
            const uint32_t bHi = buf + SB_HI + boff + ks * 32;

            uint32_t fAhi[MT][4], fBhi[NT][2];
#pragma unroll
            for (int mt = 0; mt < MT; mt++)
                ldsm4(fAhi[mt], aHi + mt * 16 * RS);
#pragma unroll
            for (int nt = 0; nt < NT; nt += 2)
                ldsm4(&fBhi[nt][0], bHi + nt * 8 * RS);

#pragma unroll
            for (int mt = 0; mt < MT; mt++)
#pragma unroll
                for (int nt = 0; nt < NT; nt++)
                    mma16816(acc[mt][nt], fAhi[mt], fBhi[nt]);
        }
    }

    // output target for OUTMODE 2 (block never straddles NM boundary: 768 % 128 == 0)
    float* Cout = nullptr;
    int cstride = 0, cbase = 0;
    if (OUTMODE == 2) {
        if (blockN < NM) { Cout = Cf0; cstride = NM; cbase = blockN; }
        else             { Cout = Cf1; cstride = NV; cbase = blockN - NM; }
    }

    // epilogue
#pragma unroll
    for (int mt = 0; mt < MT; mt++) {
        const int row0 = blockM + m0 + mt * 16 + g;
#pragma unroll
        for (int nt = 0; nt < NT; nt++) {
            const int coll = n0 + nt * 8 + 2 * t;
            const float bv0 = sBias[coll], bv1 = sBias[coll + 1];
            float v00 = acc[mt][nt][0] + bv0, v01 = acc[mt][nt][1] + bv1;
            float v10 = acc[mt][nt][2] + bv0, v11 = acc[mt][nt][3] + bv1;
            if (SILU) {
                v00 = v00 / (1.f + expf(-v00));
                v01 = v01 / (1.f + expf(-v01));
                v10 = v10 / (1.f + expf(-v10));
                v11 = v11 / (1.f + expf(-v11));
            }
            if (OUTMODE == 2) {
                const int col = cbase + coll;
                float2 a = {v00, v01}, b = {v10, v11};
                *(float2*)(Cout + (size_t)row0 * cstride + col)       = a;
                *(float2*)(Cout + (size_t)(row0 + 8) * cstride + col) = b;
            } else {
                const int col = blockN + coll;
                size_t p0 = (size_t)row0 * HID + col;
                size_t p1 = (size_t)(row0 + 8) * HID + col;
                *(uint32_t*)(Chi + p0) = hpack2(v00, v01);
                *(uint32_t*)(Chi + p1) = hpack2(v10, v11);
            }
        }
    }
}

// ---------------------------------------------------------------------------
// MVN epilogue: 16 threads per (b,h) group, float4 stores, fp32 lv input.
// ---------------------------------------------------------------------------
__device__ __forceinline__ int triu_idx(int r, int c) {
    return r * (15 - r) / 2 + (c - r - 1);
}

__global__ __launch_bounds__(256)
void mvn_epilogue(const float* __restrict__ lv,
                  float* __restrict__ prec,
                  float* __restrict__ Dout,
                  float* __restrict__ Tout)
{
    constexpr int GP = 16;                 // groups per block (16 threads each)
    __shared__ float s_eta[GP][E_DIM];
    __shared__ float s_d[GP][O_DIM];
    __shared__ float s_dinv[GP][O_DIM];

    const int g = threadIdx.x >> 4;        // 0..15
    const int s = threadIdx.x & 15;        // 0..15
    const size_t bh = (size_t)blockIdx.x * GP + g;

#pragma unroll
    for (int e = s; e < E_DIM; e += 16)
        s_eta[g][e] = lv[bh * E_DIM + e];
    __syncthreads();
    if (s < O_DIM) {
        float d = expf(0.5f * s_eta[g][s]);
        s_d[g][s] = d;
        s_dinv[g][s] = 1.f / d;
    }
    __syncthreads();

    const int i  = s >> 1;                 // row 0..7
    const int kb = (s & 1) * 4;            // col base 0 or 4
    const float* e = s_eta[g];
    const float* dinv = s_dinv[g];

    float pv[4] = {0.f, 0.f, 0.f, 0.f};
    float tv[4], dv[4];
#pragma unroll
    for (int c = 0; c < 4; c++) {
        const int k = kb + c;
        tv[c] = (i == k) ? 1.f : ((i < k) ? e[O_DIM + triu_idx(i, k)] : 0.f);
        dv[c] = (i == k) ? s_d[g][i] : 0.f;
    }
#pragma unroll
    for (int j = 0; j < O_DIM; j++) {
        float tji = (j == i) ? 1.f : ((j < i) ? e[O_DIM + triu_idx(j, i)] : 0.f);
        float w = tji * dinv[j];
#pragma unroll
        for (int c = 0; c < 4; c++) {
            const int k = kb + c;
            float tjk = (j == k) ? 1.f : ((j < k) ? e[O_DIM + triu_idx(j, k)] : 0.f);
            pv[c] = fmaf(w, tjk, pv[c]);
        }
    }

    const size_t base = bh * (O_DIM * O_DIM) + i * O_DIM + kb;
    *(float4*)(prec + base) = *(float4*)pv;
    *(float4*)(Dout + base) = *(float4*)dv;
    *(float4*)(Tout + base) = *(float4*)tv;
}

// ---------------------------------------------------------------------------
// Launch
// ---------------------------------------------------------------------------
extern "C" void kernel_launch(void* const* d_in, const int* in_sizes, int n_in,
                              void* d_out, int out_size)
{
    const float* z  = (const float*)d_in[0];
    const float* W1 = (const float*)d_in[1];
    const float* b1 = (const float*)d_in[2];
    const float* W2 = (const float*)d_in[3];
    const float* b2 = (const float*)d_in[4];
    const float* Wm = (const float*)d_in[5];
    const float* bm = (const float*)d_in[6];
    const float* Wv = (const float*)d_in[7];
    const float* bv = (const float*)d_in[8];

    float* out = (float*)d_out;
    const size_t n_means = (size_t)BATCH * FH * O_DIM;
    const size_t n_mat   = (size_t)BATCH * FH * O_DIM * O_DIM;
    float* means = out;
    float* prec  = out + n_means;
    float* Dout  = prec + n_mat;
    float* Tout  = Dout + n_mat;

    __half *zhi, *ihi, *hhi, *w1hi, *w2hi, *wchi;
    float *lv, *bcat;
    cudaGetSymbolAddress((void**)&zhi, g_zhi);
    cudaGetSymbolAddress((void**)&ihi, g_ihi);
    cudaGetSymbolAddress((void**)&hhi, g_hhi);
    cudaGetSymbolAddress((void**)&w1hi, g_w1hi);
    cudaGetSymbolAddress((void**)&w2hi, g_w2hi);
    cudaGetSymbolAddress((void**)&wchi, g_wchi);
    cudaGetSymbolAddress((void**)&bcat, g_bcat);
    cudaGetSymbolAddress((void**)&lv, g_lv);

    const int SMEM = 3 * 20480 + 512;   // 61952
    cudaFuncSetAttribute((void*)gemm_mma<true, 3>,  cudaFuncAttributeMaxDynamicSharedMemorySize, SMEM);
    cudaFuncSetAttribute((void*)gemm_mma<false, 3>, cudaFuncAttributeMaxDynamicSharedMemorySize, SMEM);
    cudaFuncSetAttribute((void*)gemm_mma<false, 2>, cudaFuncAttributeMaxDynamicSharedMemorySize, SMEM);

    // single prep launch: all weight converts + z convert + bias concat
    prep_all<<<dim3(228, 32), 256>>>(W1, W2, Wm, Wv, z,
                                     w1hi, w2hi, wchi, zhi, bm, bv, bcat);

    // GEMM chain (single-pass fp16, CTA 128x128, BK=32, 3-stage, 2 CTAs/SM)
    gemm_mma<true, 3><<<dim3(HID / 128, BATCH / 128), 256, SMEM>>>(
        zhi, w1hi, b1, nullptr, nullptr, ihi);
    gemm_mma<false, 3><<<dim3(HID / 128, BATCH / 128), 256, SMEM>>>(
        ihi, w2hi, b2, nullptr, nullptr, hhi);
    gemm_mma<false, 2><<<dim3(NCAT / 128, BATCH / 128), 256, SMEM>>>(
        hhi, wchi, bcat, means, lv, nullptr);

    // MVN epilogue (16 groups/block, float4 stores, fp32 lv)
    mvn_epilogue<<<(BATCH * FH) / 16, 256>>>(lv, prec, Dout, Tout);
}